// round 7
// baseline (speedup 1.0000x reference)
#include <cuda_runtime.h>
#include <math.h>

#define BB 8
#define TT 2048
#define EE 1024
#define DD 128
#define BT (BB*TT)

#define BR 128          // attn q-tile rows
#define BC 64           // attn kv-tile
#define CH 6            // kv64 tiles per chunk
#define NCMAX 6
#define QTN (TT/BR)     // 16

// Device scratch (no allocations allowed)
__device__ float g_wt[3*EE*DD];            // W^T per z: [n][k], tf32-rounded
__device__ float g_q[BT*DD];               // q*scale, tf32-rounded
__device__ float g_k[BT*DD];               // tf32-rounded
__device__ float g_vT[BT*DD];              // V^T per batch: [b][d][s], tf32
__device__ float g_Op[(size_t)QTN*NCMAX*BB*BR*DD];  // unnormalized partial O
__device__ float g_ml[QTN*NCMAX*BB*2*128];          // per-chunk m,l per row

__device__ __forceinline__ unsigned f2tf(float x) {
    unsigned u;
    asm("cvt.rna.tf32.f32 %0, %1;" : "=r"(u) : "f"(x));
    return u;
}
__device__ __forceinline__ float f2tff(float x) { return __uint_as_float(f2tf(x)); }

__device__ __forceinline__ void cpa16(unsigned* dst, const void* src) {
    unsigned d = (unsigned)__cvta_generic_to_shared(dst);
    asm volatile("cp.async.cg.shared.global [%0], [%1], 16;\n" :: "r"(d), "l"(src));
}
__device__ __forceinline__ void cp_commit() { asm volatile("cp.async.commit_group;\n"); }
template<int N> __device__ __forceinline__ void cp_wait() {
    asm volatile("cp.async.wait_group %0;\n" :: "n"(N));
}

__device__ __forceinline__ void mma8(float* d, const unsigned* a, const unsigned* b) {
    asm volatile(
        "mma.sync.aligned.m16n8k8.row.col.f32.tf32.tf32.f32 "
        "{%0,%1,%2,%3}, {%4,%5,%6,%7}, {%8,%9}, {%0,%1,%2,%3};\n"
        : "+f"(d[0]), "+f"(d[1]), "+f"(d[2]), "+f"(d[3])
        : "r"(a[0]), "r"(a[1]), "r"(a[2]), "r"(a[3]), "r"(b[0]), "r"(b[1]));
}

__device__ __forceinline__ void ldm4(unsigned& r0, unsigned& r1, unsigned& r2,
                                     unsigned& r3, const unsigned* p) {
    unsigned a = (unsigned)__cvta_generic_to_shared(p);
    asm volatile("ldmatrix.sync.aligned.m8n8.x4.shared.b16 {%0,%1,%2,%3}, [%4];"
                 : "=r"(r0), "=r"(r1), "=r"(r2), "=r"(r3) : "r"(a));
}

// ---------------------------------------------------------------------------
// Kernel 0: round + transpose W only (x is consumed raw by proj).
// ---------------------------------------------------------------------------
__global__ __launch_bounds__(256) void cvt_w_kernel(const float* __restrict__ Wk,
                                                    const float* __restrict__ Wq,
                                                    const float* __restrict__ Wv)
{
    const int NW = EE*DD/4;
    int i = blockIdx.x * 256 + threadIdx.x;
    if (i >= 3*NW) return;
    int z = i / NW, p = i - z*NW;
    const float4* src = (const float4*)((z == 0) ? Wq : (z == 1) ? Wk : Wv);
    float4 v = src[p];                 // W[k][4nq..4nq+3]
    int k = p >> 5;                    // DD/4 == 32
    int nq = p & 31;
    float* dst = g_wt + (size_t)z * EE * DD;
    dst[(size_t)(4*nq + 0)*EE + k] = f2tff(v.x);
    dst[(size_t)(4*nq + 1)*EE + k] = f2tff(v.y);
    dst[(size_t)(4*nq + 2)*EE + k] = f2tff(v.z);
    dst[(size_t)(4*nq + 3)*EE + k] = f2tff(v.w);
}

// ---------------------------------------------------------------------------
// Kernel 1: QKV projection. Reads RAW x (rounds A-frags in regs), W^T rounded.
// Grid (3, M/128): z fastest -> the 3 z-blocks of one m-tile co-resident -> L2
// reuse of x. Block tile 128x128, 8 warps, warp tile 64x32, BK=32, 3-stage.
// ---------------------------------------------------------------------------
#define AP 36
#define BP2 36
#define A_ST (128*AP)
#define B_ST (128*BP2)

__global__ __launch_bounds__(256, 2) void proj_kernel(const float* __restrict__ x)
{
    extern __shared__ unsigned psm[];
    unsigned* As = psm;
    unsigned* Bs = psm + 3*A_ST;

    const int tid = threadIdx.x;
    const int wid = tid >> 5;
    const int lane = tid & 31;
    const int r = lane >> 2;
    const int c = lane & 3;
    const int g8 = lane >> 3;
    const int rw = lane & 7;
    const int mi = wid >> 2;
    const int nj = wid & 3;
    const int z = blockIdx.x;
    const int m0 = blockIdx.y * 128;

    const float* Wz = g_wt + (size_t)z * EE * DD;   // [n][k]

    auto load_tile = [&](int st, int k0) {
#pragma unroll
        for (int it = 0; it < 4; ++it) {
            int linear = tid + 256 * it;
            int m = linear >> 3, g = linear & 7;
            cpa16(&As[st*A_ST + m*AP + 4*g], &x[(size_t)(m0 + m)*EE + k0 + 4*g]);
        }
#pragma unroll
        for (int it = 0; it < 4; ++it) {
            int linear = tid + 256 * it;
            int n = linear >> 3, g = linear & 7;
            cpa16(&Bs[st*B_ST + n*BP2 + 4*g], &Wz[(size_t)n*EE + k0 + 4*g]);
        }
    };

    load_tile(0, 0);  cp_commit();
    load_tile(1, 32); cp_commit();

    float acc[4][4][4];
#pragma unroll
    for (int mt = 0; mt < 4; ++mt)
#pragma unroll
        for (int nt = 0; nt < 4; ++nt)
#pragma unroll
            for (int f = 0; f < 4; ++f) acc[mt][nt][f] = 0.f;

    const int aoff = (64*mi + (g8 & 1)*8 + rw)*AP + (g8 >> 1)*4;
    const int boff = (32*nj + 8*(g8 >> 1) + rw)*BP2 + 4*(g8 & 1);

    for (int kt = 0; kt < 32; ++kt) {
        cp_wait<1>();
        __syncthreads();
        if (kt + 2 < 32) load_tile((kt + 2) % 3, 32 * (kt + 2));
        cp_commit();

        const unsigned* A = As + (kt % 3) * A_ST;
        const unsigned* B = Bs + (kt % 3) * B_ST;
#pragma unroll
        for (int kk = 0; kk < 4; ++kk) {
            unsigned a[4][4], b[4][2];
#pragma unroll
            for (int mt = 0; mt < 4; ++mt) {
                ldm4(a[mt][0], a[mt][1], a[mt][2], a[mt][3],
                     A + aoff + mt*16*AP + 8*kk);
#pragma unroll
                for (int i = 0; i < 4; ++i)        // round raw x to tf32 in regs
                    a[mt][i] = f2tf(__uint_as_float(a[mt][i]));
            }
            ldm4(b[0][0], b[0][1], b[1][0], b[1][1], B + boff + 8*kk);
            ldm4(b[2][0], b[2][1], b[3][0], b[3][1], B + boff + 16*BP2 + 8*kk);
#pragma unroll
            for (int mt = 0; mt < 4; ++mt)
#pragma unroll
                for (int nt = 0; nt < 4; ++nt)
                    mma8(acc[mt][nt], a[mt], b[nt]);
        }
    }

    if (z == 2) {
        // write V transposed: g_vT[b][d][t]
#pragma unroll
        for (int mt = 0; mt < 4; ++mt) {
            int row0 = m0 + 64 * mi + 16 * mt + r;
            float* vt = g_vT + (size_t)(row0 >> 11) * DD * TT;
            int t = row0 & (TT - 1);
#pragma unroll
            for (int nt = 0; nt < 4; ++nt) {
                int col = 32 * nj + 8 * nt + 2 * c;
                vt[(size_t)col * TT + t]           = f2tff(acc[mt][nt][0]);
                vt[(size_t)(col + 1) * TT + t]     = f2tff(acc[mt][nt][1]);
                vt[(size_t)col * TT + t + 8]       = f2tff(acc[mt][nt][2]);
                vt[(size_t)(col + 1) * TT + t + 8] = f2tff(acc[mt][nt][3]);
            }
        }
    } else {
        float* out = (z == 0) ? g_q : g_k;
        const float mul = (z == 0) ? 0.08838834764831845f : 1.f;
#pragma unroll
        for (int mt = 0; mt < 4; ++mt) {
            int row0 = m0 + 64 * mi + 16 * mt + r;
#pragma unroll
            for (int nt = 0; nt < 4; ++nt) {
                int col = 32 * nj + 8 * nt + 2 * c;
                *(float2*)&out[(size_t)row0 * DD + col] =
                    make_float2(f2tff(acc[mt][nt][0]*mul), f2tff(acc[mt][nt][1]*mul));
                *(float2*)&out[(size_t)(row0 + 8) * DD + col] =
                    make_float2(f2tff(acc[mt][nt][2]*mul), f2tff(acc[mt][nt][3]*mul));
            }
        }
    }
}

// ---------------------------------------------------------------------------
// Kernel 2: causal flash attention, Br=128, Bc=64, chunked kv (flash-decoding
// style). 8 warps: mi=wid&3 (32 rows), ni=wid>>2 (half of n / d cols).
// Warp tiles: S 32x32, O 32x64. Q in smem (ldmatrix per kc). VT double-buffer,
// K single buffer with post-S prefetch. Writes unnormalized (O,m,l) partials.
// ---------------------------------------------------------------------------
#define QP 132
#define KP 132
#define VTP 68
#define PP 68
#define Q_SZ (128*QP)     // 16896
#define K_SZ (64*KP)      //  8448
#define VT_SZ (128*VTP)   //  8704
#define P_SZ (128*PP)     //  8704
#define OFF_K  Q_SZ
#define OFF_VT (OFF_K + K_SZ)
#define OFF_P  (OFF_VT + 2*VT_SZ)
#define OFF_MX (OFF_P + P_SZ)
#define OFF_SS (OFF_MX + 256)
#define ATTN_SMEM_W (OFF_SS + 256)   // 51968 words = 207,872 B

__global__ __launch_bounds__(256) void attn_kernel()
{
    extern __shared__ unsigned sm[];
    unsigned* Qs = sm;
    unsigned* Ks = sm + OFF_K;
    unsigned* Ps = sm + OFF_P;
    float* smax = (float*)(sm + OFF_MX);
    float* ssum = (float*)(sm + OFF_SS);

    const int ch = blockIdx.x;
    const int qt = blockIdx.y;
    const int b  = blockIdx.z;
    const int nT = 2*qt + 2;
    const int tgS = ch*CH;
    if (tgS >= nT) return;
    const int tgE = (tgS + CH < nT) ? (tgS + CH) : nT;
    const int t0 = qt * BR;
    const size_t base = (size_t)b * TT;

    const int tid = threadIdx.x;
    const int wid = tid >> 5;
    const int lane = tid & 31;
    const int r = lane >> 2;
    const int c = lane & 3;
    const int g8 = lane >> 3;
    const int rw = lane & 7;
    const int mi = wid & 3;
    const int ni = wid >> 2;

    auto load_k = [&](int s0) {
#pragma unroll
        for (int it = 0; it < 8; ++it) {
            int linear = tid + 256 * it;         // 64 rows x 32 f4
            int row = linear >> 5, g = linear & 31;
            cpa16(&Ks[row*KP + 4*g], &g_k[(base + s0 + row)*DD + 4*g]);
        }
    };
    auto load_vt = [&](int st, int s0) {
        unsigned* Vd = sm + OFF_VT + st*VT_SZ;
#pragma unroll
        for (int it = 0; it < 8; ++it) {
            int linear = tid + 256 * it;         // 128 rows x 16 f4
            int row = linear >> 4, g = linear & 15;
            cpa16(&Vd[row*VTP + 4*g],
                  &g_vT[((size_t)b*DD + row)*TT + s0 + 4*g]);
        }
    };

    // prologue: Q + K(tgS) + VT(tgS) in one group
#pragma unroll
    for (int it = 0; it < 16; ++it) {
        int linear = tid + 256 * it;             // 128 rows x 32 f4
        int row = linear >> 5, g = linear & 31;
        cpa16(&Qs[row*QP + 4*g], &g_q[(base + t0 + row)*DD + 4*g]);
    }
    load_k(BC*tgS);
    load_vt(0, BC*tgS);
    cp_commit();

    float oacc[2][8][4];
#pragma unroll
    for (int mt = 0; mt < 2; ++mt)
#pragma unroll
        for (int nt = 0; nt < 8; ++nt)
#pragma unroll
            for (int f = 0; f < 4; ++f) oacc[mt][nt][f] = 0.f;
    float m_run[4] = {-INFINITY, -INFINITY, -INFINITY, -INFINITY};
    float l_part[4] = {0.f, 0.f, 0.f, 0.f};

    const int qoff = (32*mi + (g8 & 1)*8 + rw)*QP + (g8 >> 1)*4;
    const int koff = (32*ni + 8*(g8 >> 1) + rw)*KP + 4*(g8 & 1);
    const int poff = (32*mi + (g8 & 1)*8 + rw)*PP + (g8 >> 1)*4;
    const int voff = (64*ni + 8*(g8 >> 1) + rw)*VTP + 4*(g8 & 1);

    for (int tg = tgS, tt = 0; tg < tgE; ++tg, ++tt) {
        cp_wait<0>();
        __syncthreads();                         // K(tg), VT(tg), Q ready; all warps past tg-1
        const unsigned* Vc = sm + OFF_VT + (tt & 1)*VT_SZ;
        if (tg + 1 < tgE) load_vt((tt + 1) & 1, BC*(tg + 1));
        cp_commit();

        const int s0 = BC*tg;

        // ---- S = Q K^T : warp computes 32 rows x 32 cols ----
        float sacc[2][4][4];
#pragma unroll
        for (int mt = 0; mt < 2; ++mt)
#pragma unroll
            for (int nt = 0; nt < 4; ++nt)
#pragma unroll
                for (int f = 0; f < 4; ++f) sacc[mt][nt][f] = 0.f;

#pragma unroll
        for (int kc = 0; kc < 16; ++kc) {
            unsigned qa[8], kb[4][2];
            ldm4(qa[0], qa[1], qa[2], qa[3], Qs + qoff + 8*kc);
            ldm4(qa[4], qa[5], qa[6], qa[7], Qs + qoff + 16*QP + 8*kc);
            ldm4(kb[0][0], kb[0][1], kb[1][0], kb[1][1], Ks + koff + 8*kc);
            ldm4(kb[2][0], kb[2][1], kb[3][0], kb[3][1], Ks + koff + 16*KP + 8*kc);
#pragma unroll
            for (int mt = 0; mt < 2; ++mt)
#pragma unroll
                for (int nt = 0; nt < 4; ++nt)
                    mma8(sacc[mt][nt], qa + 4*mt, kb[nt]);
        }

        // ---- causal mask (last two global tiles only) ----
        if (tg >= 2*qt) {
#pragma unroll
            for (int mt = 0; mt < 2; ++mt)
#pragma unroll
                for (int nt = 0; nt < 4; ++nt)
#pragma unroll
                    for (int f = 0; f < 4; ++f) {
                        int rowg = t0 + 32*mi + 16*mt + r + ((f >= 2) ? 8 : 0);
                        int colg = s0 + 32*ni + 8*nt + 2*c + (f & 1);
                        if (colg > rowg) sacc[mt][nt][f] = -1e30f;
                    }
        }

        // ---- row max (own 32 cols), exchange within ni-pair ----
        float pmax[4];
#pragma unroll
        for (int mt = 0; mt < 2; ++mt)
#pragma unroll
            for (int h = 0; h < 2; ++h) {
                float mx = -INFINITY;
#pragma unroll
                for (int nt = 0; nt < 4; ++nt) {
                    mx = fmaxf(mx, sacc[mt][nt][2*h]);
                    mx = fmaxf(mx, sacc[mt][nt][2*h + 1]);
                }
                mx = fmaxf(mx, __shfl_xor_sync(0xffffffffu, mx, 1));
                mx = fmaxf(mx, __shfl_xor_sync(0xffffffffu, mx, 2));
                pmax[2*mt + h] = mx;
            }
        if (c == 0) {
#pragma unroll
            for (int s = 0; s < 4; ++s)
                smax[ni*128 + 32*mi + 16*(s >> 1) + r + 8*(s & 1)] = pmax[s];
        }
        asm volatile("bar.sync %0, 64;" :: "r"(1 + mi));

        float m_new[4], alpha[4];
#pragma unroll
        for (int s = 0; s < 4; ++s) {
            int row = 32*mi + 16*(s >> 1) + r + 8*(s & 1);
            float mo = fmaxf(smax[row], smax[128 + row]);
            m_new[s] = fmaxf(m_run[s], mo);
            alpha[s] = __expf(m_run[s] - m_new[s]);
            m_run[s] = m_new[s];
        }

        // ---- exp, write P (tf32), accumulate own-half row sum ----
#pragma unroll
        for (int mt = 0; mt < 2; ++mt)
#pragma unroll
            for (int h = 0; h < 2; ++h) {
                const int s = 2*mt + h;
                float s_ = 0.f;
#pragma unroll
                for (int nt = 0; nt < 4; ++nt) {
                    float p0 = __expf(sacc[mt][nt][2*h] - m_new[s]);
                    float p1 = __expf(sacc[mt][nt][2*h + 1] - m_new[s]);
                    s_ += p0 + p1;
                    *(uint2*)&Ps[(32*mi + 16*mt + r + 8*h)*PP + 32*ni + 8*nt + 2*c] =
                        make_uint2(f2tf(p0), f2tf(p1));
                }
                s_ += __shfl_xor_sync(0xffffffffu, s_, 1);
                s_ += __shfl_xor_sync(0xffffffffu, s_, 2);
                l_part[s] = l_part[s] * alpha[s] + s_;
            }

        __syncthreads();             // P visible to all; K reads finished
        if (tg + 1 < tgE) load_k(BC*(tg + 1));
        cp_commit();

        // ---- rescale O ----
#pragma unroll
        for (int mt = 0; mt < 2; ++mt)
#pragma unroll
            for (int nt = 0; nt < 8; ++nt) {
                oacc[mt][nt][0] *= alpha[2*mt];
                oacc[mt][nt][1] *= alpha[2*mt];
                oacc[mt][nt][2] *= alpha[2*mt + 1];
                oacc[mt][nt][3] *= alpha[2*mt + 1];
            }

        // ---- O += P V : warp computes 32 rows x 64 cols ----
#pragma unroll
        for (int kc2 = 0; kc2 < 8; ++kc2) {
            unsigned pa[8], vb[8][2];
            ldm4(pa[0], pa[1], pa[2], pa[3], Ps + poff + 8*kc2);
            ldm4(pa[4], pa[5], pa[6], pa[7], Ps + poff + 16*PP + 8*kc2);
            ldm4(vb[0][0], vb[0][1], vb[1][0], vb[1][1], Vc + voff + 8*kc2);
            ldm4(vb[2][0], vb[2][1], vb[3][0], vb[3][1], Vc + voff + 16*VTP + 8*kc2);
            ldm4(vb[4][0], vb[4][1], vb[5][0], vb[5][1], Vc + voff + 32*VTP + 8*kc2);
            ldm4(vb[6][0], vb[6][1], vb[7][0], vb[7][1], Vc + voff + 48*VTP + 8*kc2);
#pragma unroll
            for (int mt = 0; mt < 2; ++mt)
#pragma unroll
                for (int nt = 0; nt < 8; ++nt)
                    mma8(oacc[mt][nt], pa + 4*mt, vb[nt]);
        }
    }

    // ---- epilogue: combine l halves across ni-pair, write partials ----
    if (c == 0) {
#pragma unroll
        for (int s = 0; s < 4; ++s)
            ssum[ni*128 + 32*mi + 16*(s >> 1) + r + 8*(s & 1)] = l_part[s];
    }
    asm volatile("bar.sync %0, 64;" :: "r"(1 + mi));

    const int slot = (qt*NCMAX + ch)*BB + b;
    if (ni == 0 && c == 0) {
#pragma unroll
        for (int s = 0; s < 4; ++s) {
            int row = 32*mi + 16*(s >> 1) + r + 8*(s & 1);
            g_ml[slot*256 + row]       = m_run[s];
            g_ml[slot*256 + 128 + row] = l_part[s] + ssum[128 + row];  // ni==0 adds ni==1 half
        }
    }
    float* op = g_Op + (size_t)slot * BR * DD;
#pragma unroll
    for (int mt = 0; mt < 2; ++mt) {
        int row0 = 32*mi + 16*mt + r;
#pragma unroll
        for (int nt = 0; nt < 8; ++nt) {
            int col = 64*ni + 8*nt + 2*c;
            *(float2*)&op[(size_t)row0*DD + col] =
                make_float2(oacc[mt][nt][0], oacc[mt][nt][1]);
            *(float2*)&op[(size_t)(row0 + 8)*DD + col] =
                make_float2(oacc[mt][nt][2], oacc[mt][nt][3]);
        }
    }
}

// ---------------------------------------------------------------------------
// Kernel 3: combine chunk partials -> normalized output.
// Grid 128 blocks (qt,b), 256 threads; thread = (row, d-half).
// ---------------------------------------------------------------------------
__global__ __launch_bounds__(256) void combine_kernel(float* __restrict__ out)
{
    const int blk = blockIdx.x;
    const int qt = blk >> 3, b = blk & 7;
    const int nc = (2*qt + 2 + CH - 1) / CH;
    const int tid = threadIdx.x;
    const int row = tid >> 1;
    const int dh = (tid & 1) * 64;
    const int t0 = qt * BR;

    float M = -INFINITY;
    for (int cc = 0; cc < nc; ++cc) {
        int slot = (qt*NCMAX + cc)*BB + b;
        M = fmaxf(M, g_ml[slot*256 + row]);
    }
    float L = 0.f;
    for (int cc = 0; cc < nc; ++cc) {
        int slot = (qt*NCMAX + cc)*BB + b;
        L += __expf(g_ml[slot*256 + row] - M) * g_ml[slot*256 + 128 + row];
    }
    const float inv = 1.f / L;

    float4 acc[16];
#pragma unroll
    for (int i = 0; i < 16; ++i) acc[i] = make_float4(0.f, 0.f, 0.f, 0.f);
    for (int cc = 0; cc < nc; ++cc) {
        int slot = (qt*NCMAX + cc)*BB + b;
        float w = __expf(g_ml[slot*256 + row] - M);
        const float4* src = (const float4*)&g_Op[((size_t)slot*BR + row)*DD + dh];
#pragma unroll
        for (int i = 0; i < 16; ++i) {
            float4 v = src[i];
            acc[i].x += w*v.x; acc[i].y += w*v.y;
            acc[i].z += w*v.z; acc[i].w += w*v.w;
        }
    }
    float4* dst = (float4*)&out[((size_t)b*TT + t0 + row)*DD + dh];
#pragma unroll
    for (int i = 0; i < 16; ++i) {
        acc[i].x *= inv; acc[i].y *= inv; acc[i].z *= inv; acc[i].w *= inv;
        dst[i] = acc[i];
    }
}

// ---------------------------------------------------------------------------
extern "C" void kernel_launch(void* const* d_in, const int* in_sizes, int n_in,
                              void* d_out, int out_size)
{
    (void)in_sizes; (void)n_in; (void)out_size;
    const float* x  = (const float*)d_in[0];
    const float* Wk = (const float*)d_in[1];
    const float* Wq = (const float*)d_in[2];
    const float* Wv = (const float*)d_in[3];
    float* out = (float*)d_out;

    const int NW3 = 3*EE*DD/4;
    cvt_w_kernel<<<(NW3 + 255)/256, 256>>>(Wk, Wq, Wv);

    const int proj_smem = (3*A_ST + 3*B_ST) * 4;       // 110,592 B
    cudaFuncSetAttribute(proj_kernel,
                         cudaFuncAttributeMaxDynamicSharedMemorySize, proj_smem);
    dim3 pgrid(3, BT/128);                             // z fastest -> L2 reuse of x
    proj_kernel<<<pgrid, 256, proj_smem>>>(x);

    const int attn_smem = ATTN_SMEM_W * 4;             // 207,872 B
    cudaFuncSetAttribute(attn_kernel,
                         cudaFuncAttributeMaxDynamicSharedMemorySize, attn_smem);
    dim3 agrid(NCMAX, QTN, BB);                        // (chunk, qtile, batch)
    attn_kernel<<<agrid, 256, attn_smem>>>();

    combine_kernel<<<QTN*BB, 256>>>(out);
}

// round 8
// speedup vs baseline: 1.0715x; 1.0715x over previous
#include <cuda_runtime.h>
#include <math.h>

#define BB 8
#define TT 2048
#define EE 1024
#define DD 128
#define BT (BB*TT)

#define BR 128          // attn q-tile rows
#define BC 64           // attn kv-tile
#define CH 6            // kv64 tiles per chunk
#define NCMAX 6
#define QTN (TT/BR)     // 16

// Device scratch (no allocations allowed)
__device__ float g_wt[3*EE*DD];            // W^T per z: [n][k], tf32-rounded
__device__ float g_q[BT*DD];               // q*scale, tf32-rounded
__device__ float g_k[BT*DD];               // tf32-rounded
__device__ float g_vT[BT*DD];              // V^T per batch: [b][d][s], tf32
__device__ float g_Op[(size_t)QTN*NCMAX*BB*BR*DD];  // unnormalized partial O
__device__ float g_ml[QTN*NCMAX*BB*2*128];          // per-chunk m,l per row

__device__ __forceinline__ unsigned f2tf(float x) {
    unsigned u;
    asm("cvt.rna.tf32.f32 %0, %1;" : "=r"(u) : "f"(x));
    return u;
}
__device__ __forceinline__ float f2tff(float x) { return __uint_as_float(f2tf(x)); }

__device__ __forceinline__ void cpa16(unsigned* dst, const void* src) {
    unsigned d = (unsigned)__cvta_generic_to_shared(dst);
    asm volatile("cp.async.cg.shared.global [%0], [%1], 16;\n" :: "r"(d), "l"(src));
}
__device__ __forceinline__ void cp_commit() { asm volatile("cp.async.commit_group;\n"); }
template<int N> __device__ __forceinline__ void cp_wait() {
    asm volatile("cp.async.wait_group %0;\n" :: "n"(N));
}

__device__ __forceinline__ void mma8(float* d, const unsigned* a, const unsigned* b) {
    asm volatile(
        "mma.sync.aligned.m16n8k8.row.col.f32.tf32.tf32.f32 "
        "{%0,%1,%2,%3}, {%4,%5,%6,%7}, {%8,%9}, {%0,%1,%2,%3};\n"
        : "+f"(d[0]), "+f"(d[1]), "+f"(d[2]), "+f"(d[3])
        : "r"(a[0]), "r"(a[1]), "r"(a[2]), "r"(a[3]), "r"(b[0]), "r"(b[1]));
}

__device__ __forceinline__ void ldm4(unsigned& r0, unsigned& r1, unsigned& r2,
                                     unsigned& r3, const unsigned* p) {
    unsigned a = (unsigned)__cvta_generic_to_shared(p);
    asm volatile("ldmatrix.sync.aligned.m8n8.x4.shared.b16 {%0,%1,%2,%3}, [%4];"
                 : "=r"(r0), "=r"(r1), "=r"(r2), "=r"(r3) : "r"(a));
}

// ---------------------------------------------------------------------------
// Kernel 0: round + transpose W only (x is consumed raw by proj).
// ---------------------------------------------------------------------------
__global__ __launch_bounds__(256) void cvt_w_kernel(const float* __restrict__ Wk,
                                                    const float* __restrict__ Wq,
                                                    const float* __restrict__ Wv)
{
    const int NW = EE*DD/4;
    int i = blockIdx.x * 256 + threadIdx.x;
    if (i >= 3*NW) return;
    int z = i / NW, p = i - z*NW;
    const float4* src = (const float4*)((z == 0) ? Wq : (z == 1) ? Wk : Wv);
    float4 v = src[p];                 // W[k][4nq..4nq+3]
    int k = p >> 5;                    // DD/4 == 32
    int nq = p & 31;
    float* dst = g_wt + (size_t)z * EE * DD;
    dst[(size_t)(4*nq + 0)*EE + k] = f2tff(v.x);
    dst[(size_t)(4*nq + 1)*EE + k] = f2tff(v.y);
    dst[(size_t)(4*nq + 2)*EE + k] = f2tff(v.z);
    dst[(size_t)(4*nq + 3)*EE + k] = f2tff(v.w);
}

// ---------------------------------------------------------------------------
// Kernel 1: QKV projection. Reads RAW x (rounds A-frags in regs), W^T rounded.
// Grid (3, M/128): z fastest -> L2 reuse of x across the 3 z-blocks.
// ---------------------------------------------------------------------------
#define AP 36
#define BP2 36
#define A_ST (128*AP)
#define B_ST (128*BP2)

__global__ __launch_bounds__(256, 2) void proj_kernel(const float* __restrict__ x)
{
    extern __shared__ unsigned psm[];
    unsigned* As = psm;
    unsigned* Bs = psm + 3*A_ST;

    const int tid = threadIdx.x;
    const int wid = tid >> 5;
    const int lane = tid & 31;
    const int r = lane >> 2;
    const int c = lane & 3;
    const int g8 = lane >> 3;
    const int rw = lane & 7;
    const int mi = wid >> 2;
    const int nj = wid & 3;
    const int z = blockIdx.x;
    const int m0 = blockIdx.y * 128;

    const float* Wz = g_wt + (size_t)z * EE * DD;   // [n][k]

    auto load_tile = [&](int st, int k0) {
#pragma unroll
        for (int it = 0; it < 4; ++it) {
            int linear = tid + 256 * it;
            int m = linear >> 3, g = linear & 7;
            cpa16(&As[st*A_ST + m*AP + 4*g], &x[(size_t)(m0 + m)*EE + k0 + 4*g]);
        }
#pragma unroll
        for (int it = 0; it < 4; ++it) {
            int linear = tid + 256 * it;
            int n = linear >> 3, g = linear & 7;
            cpa16(&Bs[st*B_ST + n*BP2 + 4*g], &Wz[(size_t)n*EE + k0 + 4*g]);
        }
    };

    load_tile(0, 0);  cp_commit();
    load_tile(1, 32); cp_commit();

    float acc[4][4][4];
#pragma unroll
    for (int mt = 0; mt < 4; ++mt)
#pragma unroll
        for (int nt = 0; nt < 4; ++nt)
#pragma unroll
            for (int f = 0; f < 4; ++f) acc[mt][nt][f] = 0.f;

    const int aoff = (64*mi + (g8 & 1)*8 + rw)*AP + (g8 >> 1)*4;
    const int boff = (32*nj + 8*(g8 >> 1) + rw)*BP2 + 4*(g8 & 1);

    for (int kt = 0; kt < 32; ++kt) {
        cp_wait<1>();
        __syncthreads();
        if (kt + 2 < 32) load_tile((kt + 2) % 3, 32 * (kt + 2));
        cp_commit();

        const unsigned* A = As + (kt % 3) * A_ST;
        const unsigned* B = Bs + (kt % 3) * B_ST;
#pragma unroll
        for (int kk = 0; kk < 4; ++kk) {
            unsigned a[4][4], b[4][2];
#pragma unroll
            for (int mt = 0; mt < 4; ++mt) {
                ldm4(a[mt][0], a[mt][1], a[mt][2], a[mt][3],
                     A + aoff + mt*16*AP + 8*kk);
#pragma unroll
                for (int i = 0; i < 4; ++i)        // round raw x to tf32 in regs
                    a[mt][i] = f2tf(__uint_as_float(a[mt][i]));
            }
            ldm4(b[0][0], b[0][1], b[1][0], b[1][1], B + boff + 8*kk);
            ldm4(b[2][0], b[2][1], b[3][0], b[3][1], B + boff + 16*BP2 + 8*kk);
#pragma unroll
            for (int mt = 0; mt < 4; ++mt)
#pragma unroll
                for (int nt = 0; nt < 4; ++nt)
                    mma8(acc[mt][nt], a[mt], b[nt]);
        }
    }

    if (z == 2) {
        // write V transposed: g_vT[b][d][t]
#pragma unroll
        for (int mt = 0; mt < 4; ++mt) {
            int row0 = m0 + 64 * mi + 16 * mt + r;
            float* vt = g_vT + (size_t)(row0 >> 11) * DD * TT;
            int t = row0 & (TT - 1);
#pragma unroll
            for (int nt = 0; nt < 4; ++nt) {
                int col = 32 * nj + 8 * nt + 2 * c;
                vt[(size_t)col * TT + t]           = f2tff(acc[mt][nt][0]);
                vt[(size_t)(col + 1) * TT + t]     = f2tff(acc[mt][nt][1]);
                vt[(size_t)col * TT + t + 8]       = f2tff(acc[mt][nt][2]);
                vt[(size_t)(col + 1) * TT + t + 8] = f2tff(acc[mt][nt][3]);
            }
        }
    } else {
        float* out = (z == 0) ? g_q : g_k;
        const float mul = (z == 0) ? 0.08838834764831845f : 1.f;
#pragma unroll
        for (int mt = 0; mt < 4; ++mt) {
            int row0 = m0 + 64 * mi + 16 * mt + r;
#pragma unroll
            for (int nt = 0; nt < 4; ++nt) {
                int col = 32 * nj + 8 * nt + 2 * c;
                *(float2*)&out[(size_t)row0 * DD + col] =
                    make_float2(f2tff(acc[mt][nt][0]*mul), f2tff(acc[mt][nt][1]*mul));
                *(float2*)&out[(size_t)(row0 + 8) * DD + col] =
                    make_float2(f2tff(acc[mt][nt][2]*mul), f2tff(acc[mt][nt][3]*mul));
            }
        }
    }
}

// ---------------------------------------------------------------------------
// Kernel 2: causal flash attention, Br=128, Bc=64, chunked kv.
// Single-chunk-covers-all CTAs normalize and write `out` directly.
// ---------------------------------------------------------------------------
#define QP 132
#define KP 132
#define VTP 68
#define PP 68
#define Q_SZ (128*QP)
#define K_SZ (64*KP)
#define VT_SZ (128*VTP)
#define P_SZ (128*PP)
#define OFF_K  Q_SZ
#define OFF_VT (OFF_K + K_SZ)
#define OFF_P  (OFF_VT + 2*VT_SZ)
#define OFF_MX (OFF_P + P_SZ)
#define OFF_SS (OFF_MX + 256)
#define ATTN_SMEM_W (OFF_SS + 256)   // 207,872 B

__global__ __launch_bounds__(256) void attn_kernel(float* __restrict__ out)
{
    extern __shared__ unsigned sm[];
    unsigned* Qs = sm;
    unsigned* Ks = sm + OFF_K;
    unsigned* Ps = sm + OFF_P;
    float* smax = (float*)(sm + OFF_MX);
    float* ssum = (float*)(sm + OFF_SS);

    const int ch = blockIdx.x;
    const int qt = (QTN - 1) - blockIdx.y;      // heavy q-tiles first
    const int b  = blockIdx.z;
    const int nT = 2*qt + 2;
    const int tgS = ch*CH;
    if (tgS >= nT) return;
    const int tgE = (tgS + CH < nT) ? (tgS + CH) : nT;
    const bool direct = (tgS == 0) && (tgE == nT);   // chunk covers whole range
    const int t0 = qt * BR;
    const size_t base = (size_t)b * TT;

    const int tid = threadIdx.x;
    const int wid = tid >> 5;
    const int lane = tid & 31;
    const int r = lane >> 2;
    const int c = lane & 3;
    const int g8 = lane >> 3;
    const int rw = lane & 7;
    const int mi = wid & 3;
    const int ni = wid >> 2;

    auto load_k = [&](int s0) {
#pragma unroll
        for (int it = 0; it < 8; ++it) {
            int linear = tid + 256 * it;
            int row = linear >> 5, g = linear & 31;
            cpa16(&Ks[row*KP + 4*g], &g_k[(base + s0 + row)*DD + 4*g]);
        }
    };
    auto load_vt = [&](int st, int s0) {
        unsigned* Vd = sm + OFF_VT + st*VT_SZ;
#pragma unroll
        for (int it = 0; it < 8; ++it) {
            int linear = tid + 256 * it;
            int row = linear >> 4, g = linear & 15;
            cpa16(&Vd[row*VTP + 4*g],
                  &g_vT[((size_t)b*DD + row)*TT + s0 + 4*g]);
        }
    };

    // prologue: Q + K(tgS) + VT(tgS)
#pragma unroll
    for (int it = 0; it < 16; ++it) {
        int linear = tid + 256 * it;
        int row = linear >> 5, g = linear & 31;
        cpa16(&Qs[row*QP + 4*g], &g_q[(base + t0 + row)*DD + 4*g]);
    }
    load_k(BC*tgS);
    load_vt(0, BC*tgS);
    cp_commit();

    float oacc[2][8][4];
#pragma unroll
    for (int mt = 0; mt < 2; ++mt)
#pragma unroll
        for (int nt = 0; nt < 8; ++nt)
#pragma unroll
            for (int f = 0; f < 4; ++f) oacc[mt][nt][f] = 0.f;
    float m_run[4] = {-INFINITY, -INFINITY, -INFINITY, -INFINITY};
    float l_part[4] = {0.f, 0.f, 0.f, 0.f};

    const int qoff = (32*mi + (g8 & 1)*8 + rw)*QP + (g8 >> 1)*4;
    const int koff = (32*ni + 8*(g8 >> 1) + rw)*KP + 4*(g8 & 1);
    const int poff = (32*mi + (g8 & 1)*8 + rw)*PP + (g8 >> 1)*4;
    const int voff = (64*ni + 8*(g8 >> 1) + rw)*VTP + 4*(g8 & 1);

    for (int tg = tgS, tt = 0; tg < tgE; ++tg, ++tt) {
        cp_wait<0>();
        __syncthreads();
        const unsigned* Vc = sm + OFF_VT + (tt & 1)*VT_SZ;
        if (tg + 1 < tgE) load_vt((tt + 1) & 1, BC*(tg + 1));
        cp_commit();

        const int s0 = BC*tg;

        // ---- S = Q K^T : warp computes 32 rows x 32 cols ----
        float sacc[2][4][4];
#pragma unroll
        for (int mt = 0; mt < 2; ++mt)
#pragma unroll
            for (int nt = 0; nt < 4; ++nt)
#pragma unroll
                for (int f = 0; f < 4; ++f) sacc[mt][nt][f] = 0.f;

#pragma unroll
        for (int kc = 0; kc < 16; ++kc) {
            unsigned qa[8], kb[4][2];
            ldm4(qa[0], qa[1], qa[2], qa[3], Qs + qoff + 8*kc);
            ldm4(qa[4], qa[5], qa[6], qa[7], Qs + qoff + 16*QP + 8*kc);
            ldm4(kb[0][0], kb[0][1], kb[1][0], kb[1][1], Ks + koff + 8*kc);
            ldm4(kb[2][0], kb[2][1], kb[3][0], kb[3][1], Ks + koff + 16*KP + 8*kc);
#pragma unroll
            for (int mt = 0; mt < 2; ++mt)
#pragma unroll
                for (int nt = 0; nt < 4; ++nt)
                    mma8(sacc[mt][nt], qa + 4*mt, kb[nt]);
        }

        // ---- causal mask (last two global tiles only) ----
        if (tg >= 2*qt) {
#pragma unroll
            for (int mt = 0; mt < 2; ++mt)
#pragma unroll
                for (int nt = 0; nt < 4; ++nt)
#pragma unroll
                    for (int f = 0; f < 4; ++f) {
                        int rowg = t0 + 32*mi + 16*mt + r + ((f >= 2) ? 8 : 0);
                        int colg = s0 + 32*ni + 8*nt + 2*c + (f & 1);
                        if (colg > rowg) sacc[mt][nt][f] = -1e30f;
                    }
        }

        // ---- row max, exchange within ni-pair ----
        float pmax[4];
#pragma unroll
        for (int mt = 0; mt < 2; ++mt)
#pragma unroll
            for (int h = 0; h < 2; ++h) {
                float mx = -INFINITY;
#pragma unroll
                for (int nt = 0; nt < 4; ++nt) {
                    mx = fmaxf(mx, sacc[mt][nt][2*h]);
                    mx = fmaxf(mx, sacc[mt][nt][2*h + 1]);
                }
                mx = fmaxf(mx, __shfl_xor_sync(0xffffffffu, mx, 1));
                mx = fmaxf(mx, __shfl_xor_sync(0xffffffffu, mx, 2));
                pmax[2*mt + h] = mx;
            }
        if (c == 0) {
#pragma unroll
            for (int s = 0; s < 4; ++s)
                smax[ni*128 + 32*mi + 16*(s >> 1) + r + 8*(s & 1)] = pmax[s];
        }
        asm volatile("bar.sync %0, 64;" :: "r"(1 + mi));

        float m_new[4], alpha[4];
#pragma unroll
        for (int s = 0; s < 4; ++s) {
            int row = 32*mi + 16*(s >> 1) + r + 8*(s & 1);
            float mo = fmaxf(smax[row], smax[128 + row]);
            m_new[s] = fmaxf(m_run[s], mo);
            alpha[s] = __expf(m_run[s] - m_new[s]);
            m_run[s] = m_new[s];
        }

        // ---- exp, write P (tf32), accumulate own-half row sum ----
#pragma unroll
        for (int mt = 0; mt < 2; ++mt)
#pragma unroll
            for (int h = 0; h < 2; ++h) {
                const int s = 2*mt + h;
                float s_ = 0.f;
#pragma unroll
                for (int nt = 0; nt < 4; ++nt) {
                    float p0 = __expf(sacc[mt][nt][2*h] - m_new[s]);
                    float p1 = __expf(sacc[mt][nt][2*h + 1] - m_new[s]);
                    s_ += p0 + p1;
                    *(uint2*)&Ps[(32*mi + 16*mt + r + 8*h)*PP + 32*ni + 8*nt + 2*c] =
                        make_uint2(f2tf(p0), f2tf(p1));
                }
                s_ += __shfl_xor_sync(0xffffffffu, s_, 1);
                s_ += __shfl_xor_sync(0xffffffffu, s_, 2);
                l_part[s] = l_part[s] * alpha[s] + s_;
            }

        __syncthreads();             // P visible; K reads finished
        if (tg + 1 < tgE) load_k(BC*(tg + 1));
        cp_commit();

        // ---- rescale O ----
#pragma unroll
        for (int mt = 0; mt < 2; ++mt)
#pragma unroll
            for (int nt = 0; nt < 8; ++nt) {
                oacc[mt][nt][0] *= alpha[2*mt];
                oacc[mt][nt][1] *= alpha[2*mt];
                oacc[mt][nt][2] *= alpha[2*mt + 1];
                oacc[mt][nt][3] *= alpha[2*mt + 1];
            }

        // ---- O += P V ----
#pragma unroll
        for (int kc2 = 0; kc2 < 8; ++kc2) {
            unsigned pa[8], vb[8][2];
            ldm4(pa[0], pa[1], pa[2], pa[3], Ps + poff + 8*kc2);
            ldm4(pa[4], pa[5], pa[6], pa[7], Ps + poff + 16*PP + 8*kc2);
            ldm4(vb[0][0], vb[0][1], vb[1][0], vb[1][1], Vc + voff + 8*kc2);
            ldm4(vb[2][0], vb[2][1], vb[3][0], vb[3][1], Vc + voff + 16*VTP + 8*kc2);
            ldm4(vb[4][0], vb[4][1], vb[5][0], vb[5][1], Vc + voff + 32*VTP + 8*kc2);
            ldm4(vb[6][0], vb[6][1], vb[7][0], vb[7][1], Vc + voff + 48*VTP + 8*kc2);
#pragma unroll
            for (int mt = 0; mt < 2; ++mt)
#pragma unroll
                for (int nt = 0; nt < 8; ++nt)
                    mma8(oacc[mt][nt], pa + 4*mt, vb[nt]);
        }
    }

    // ---- epilogue ----
    if (c == 0) {
#pragma unroll
        for (int s = 0; s < 4; ++s)
            ssum[ni*128 + 32*mi + 16*(s >> 1) + r + 8*(s & 1)] = l_part[s];
    }
    asm volatile("bar.sync %0, 64;" :: "r"(1 + mi));

    if (direct) {
        // normalize in-kernel, write final output
        float inv[4];
#pragma unroll
        for (int s = 0; s < 4; ++s) {
            int row = 32*mi + 16*(s >> 1) + r + 8*(s & 1);
            inv[s] = 1.f / (ssum[row] + ssum[128 + row]);
        }
#pragma unroll
        for (int mt = 0; mt < 2; ++mt) {
            int row0 = 32*mi + 16*mt + r;
#pragma unroll
            for (int nt = 0; nt < 8; ++nt) {
                int col = 64*ni + 8*nt + 2*c;
                size_t gr = base + t0 + row0;
                *(float2*)&out[gr*DD + col] =
                    make_float2(oacc[mt][nt][0]*inv[2*mt], oacc[mt][nt][1]*inv[2*mt]);
                *(float2*)&out[(gr + 8)*DD + col] =
                    make_float2(oacc[mt][nt][2]*inv[2*mt+1], oacc[mt][nt][3]*inv[2*mt+1]);
            }
        }
        return;
    }

    const int slot = (qt*NCMAX + ch)*BB + b;
    if (ni == 0 && c == 0) {
#pragma unroll
        for (int s = 0; s < 4; ++s) {
            int row = 32*mi + 16*(s >> 1) + r + 8*(s & 1);
            g_ml[slot*256 + row]       = m_run[s];
            g_ml[slot*256 + 128 + row] = l_part[s] + ssum[128 + row];
        }
    }
    float* op = g_Op + (size_t)slot * BR * DD;
#pragma unroll
    for (int mt = 0; mt < 2; ++mt) {
        int row0 = 32*mi + 16*mt + r;
#pragma unroll
        for (int nt = 0; nt < 8; ++nt) {
            int col = 64*ni + 8*nt + 2*c;
            *(float2*)&op[(size_t)row0*DD + col] =
                make_float2(oacc[mt][nt][0], oacc[mt][nt][1]);
            *(float2*)&op[(size_t)(row0 + 8)*DD + col] =
                make_float2(oacc[mt][nt][2], oacc[mt][nt][3]);
        }
    }
}

// ---------------------------------------------------------------------------
// Kernel 3: combine chunk partials. 1024 blocks: (qt,b) x 8 row-groups.
// Thread = (row within group, 8-col segment). Skips direct-written tiles.
// ---------------------------------------------------------------------------
__global__ __launch_bounds__(256) void combine_kernel(float* __restrict__ out)
{
    const int blk = blockIdx.x;               // 0..1023
    const int rg = blk & 7;                   // 16-row group
    const int qb = blk >> 3;
    const int qt = qb >> 3, b = qb & 7;
    const int nT = 2*qt + 2;
    const int nc = (nT + CH - 1) / CH;
    if (nc == 1) return;                      // direct-written by attn
    const int tid = threadIdx.x;
    const int row = rg*16 + (tid >> 4);
    const int seg = (tid & 15) * 8;
    const int t0 = qt * BR;

    float M = -INFINITY;
    for (int cc = 0; cc < nc; ++cc)
        M = fmaxf(M, g_ml[((qt*NCMAX + cc)*BB + b)*256 + row]);
    float L = 0.f;
    for (int cc = 0; cc < nc; ++cc) {
        int slot = (qt*NCMAX + cc)*BB + b;
        L += __expf(g_ml[slot*256 + row] - M) * g_ml[slot*256 + 128 + row];
    }
    const float inv = 1.f / L;

    float4 a0 = make_float4(0.f,0.f,0.f,0.f), a1 = a0;
    for (int cc = 0; cc < nc; ++cc) {
        int slot = (qt*NCMAX + cc)*BB + b;
        float w = __expf(g_ml[slot*256 + row] - M);
        const float4* src = (const float4*)&g_Op[((size_t)slot*BR + row)*DD + seg];
        float4 v0 = src[0], v1 = src[1];
        a0.x += w*v0.x; a0.y += w*v0.y; a0.z += w*v0.z; a0.w += w*v0.w;
        a1.x += w*v1.x; a1.y += w*v1.y; a1.z += w*v1.z; a1.w += w*v1.w;
    }
    float4* dst = (float4*)&out[((size_t)b*TT + t0 + row)*DD + seg];
    a0.x *= inv; a0.y *= inv; a0.z *= inv; a0.w *= inv;
    a1.x *= inv; a1.y *= inv; a1.z *= inv; a1.w *= inv;
    dst[0] = a0; dst[1] = a1;
}

// ---------------------------------------------------------------------------
extern "C" void kernel_launch(void* const* d_in, const int* in_sizes, int n_in,
                              void* d_out, int out_size)
{
    (void)in_sizes; (void)n_in; (void)out_size;
    const float* x  = (const float*)d_in[0];
    const float* Wk = (const float*)d_in[1];
    const float* Wq = (const float*)d_in[2];
    const float* Wv = (const float*)d_in[3];
    float* out = (float*)d_out;

    const int NW3 = 3*EE*DD/4;
    cvt_w_kernel<<<(NW3 + 255)/256, 256>>>(Wk, Wq, Wv);

    const int proj_smem = (3*A_ST + 3*B_ST) * 4;
    cudaFuncSetAttribute(proj_kernel,
                         cudaFuncAttributeMaxDynamicSharedMemorySize, proj_smem);
    dim3 pgrid(3, BT/128);
    proj_kernel<<<pgrid, 256, proj_smem>>>(x);

    const int attn_smem = ATTN_SMEM_W * 4;
    cudaFuncSetAttribute(attn_kernel,
                         cudaFuncAttributeMaxDynamicSharedMemorySize, attn_smem);
    dim3 agrid(NCMAX, QTN, BB);
    attn_kernel<<<agrid, 256, attn_smem>>>(out);

    combine_kernel<<<QTN*BB*8, 256>>>(out);
}

// round 9
// speedup vs baseline: 1.1672x; 1.0893x over previous
#include <cuda_runtime.h>
#include <cuda_fp16.h>
#include <math.h>

#define BB 8
#define TT 2048
#define EE 1024
#define DD 128
#define BT (BB*TT)

#define BR 128
#define BC 64
#define CH 6
#define NCMAX 6
#define QTN (TT/BR)     // 16
#define VTROWS 136      // 128 d-rows + ones row (128) + 7 zero rows

#define SCALE_L2E ((float)(0.088388347648318447 * 1.4426950408889634))

// Device scratch
__device__ float  g_wt[3*EE*DD];            // W^T per z: [n][k], tf32-rounded
__device__ float  g_q[BT*DD];               // q*scale*log2e, tf32-rounded
__device__ float  g_k[BT*DD];               // tf32-rounded
__device__ __half g_vTh[(size_t)BB*VTROWS*TT];  // V^T fp16: [b][d(136)][t]
__device__ float  g_Op[(size_t)QTN*NCMAX*BB*BR*DD];
__device__ float  g_ml[QTN*NCMAX*BB*2*128]; // per-chunk m(log2),l per row

__device__ __forceinline__ unsigned f2tf(float x) {
    unsigned u;
    asm("cvt.rna.tf32.f32 %0, %1;" : "=r"(u) : "f"(x));
    return u;
}
__device__ __forceinline__ float f2tff(float x) { return __uint_as_float(f2tf(x)); }

__device__ __forceinline__ float ex2f(float x) {
    float y; asm("ex2.approx.f32 %0, %1;" : "=f"(y) : "f"(x)); return y;
}
// pack (lo,hi) to fp16x2 and take exp2 of both in ONE MUFU op
__device__ __forceinline__ unsigned exp2_f16x2(float lo, float hi) {
    unsigned pk, pe;
    asm("cvt.rn.f16x2.f32 %0, %1, %2;" : "=r"(pk) : "f"(hi), "f"(lo));
    asm("ex2.approx.f16x2 %0, %1;" : "=r"(pe) : "r"(pk));
    return pe;
}

__device__ __forceinline__ void cpa16(unsigned* dst, const void* src) {
    unsigned d = (unsigned)__cvta_generic_to_shared(dst);
    asm volatile("cp.async.cg.shared.global [%0], [%1], 16;\n" :: "r"(d), "l"(src));
}
__device__ __forceinline__ void cp_commit() { asm volatile("cp.async.commit_group;\n"); }
template<int N> __device__ __forceinline__ void cp_wait() {
    asm volatile("cp.async.wait_group %0;\n" :: "n"(N));
}

__device__ __forceinline__ void mma8(float* d, const unsigned* a, const unsigned* b) {
    asm volatile(
        "mma.sync.aligned.m16n8k8.row.col.f32.tf32.tf32.f32 "
        "{%0,%1,%2,%3}, {%4,%5,%6,%7}, {%8,%9}, {%0,%1,%2,%3};\n"
        : "+f"(d[0]), "+f"(d[1]), "+f"(d[2]), "+f"(d[3])
        : "r"(a[0]), "r"(a[1]), "r"(a[2]), "r"(a[3]), "r"(b[0]), "r"(b[1]));
}
__device__ __forceinline__ void mma16(float* d, const unsigned* a, const unsigned* b) {
    asm volatile(
        "mma.sync.aligned.m16n8k16.row.col.f32.f16.f16.f32 "
        "{%0,%1,%2,%3}, {%4,%5,%6,%7}, {%8,%9}, {%0,%1,%2,%3};\n"
        : "+f"(d[0]), "+f"(d[1]), "+f"(d[2]), "+f"(d[3])
        : "r"(a[0]), "r"(a[1]), "r"(a[2]), "r"(a[3]), "r"(b[0]), "r"(b[1]));
}

__device__ __forceinline__ void ldm4(unsigned& r0, unsigned& r1, unsigned& r2,
                                     unsigned& r3, const unsigned* p) {
    unsigned a = (unsigned)__cvta_generic_to_shared(p);
    asm volatile("ldmatrix.sync.aligned.m8n8.x4.shared.b16 {%0,%1,%2,%3}, [%4];"
                 : "=r"(r0), "=r"(r1), "=r"(r2), "=r"(r3) : "r"(a));
}
__device__ __forceinline__ void ldm2(unsigned& r0, unsigned& r1, const unsigned* p) {
    unsigned a = (unsigned)__cvta_generic_to_shared(p);
    asm volatile("ldmatrix.sync.aligned.m8n8.x2.shared.b16 {%0,%1}, [%2];"
                 : "=r"(r0), "=r"(r1) : "r"(a));
}

// ---------------------------------------------------------------------------
// Kernel 0: round+transpose W; init ones/zero tail rows of V^T (fp16).
// ---------------------------------------------------------------------------
__global__ __launch_bounds__(256) void cvt_w_kernel(const float* __restrict__ Wk,
                                                    const float* __restrict__ Wq,
                                                    const float* __restrict__ Wv)
{
    const int NW = EE*DD/4;
    int i = blockIdx.x * 256 + threadIdx.x;
    if (i < 3*NW) {
        int z = i / NW, p = i - z*NW;
        const float4* src = (const float4*)((z == 0) ? Wq : (z == 1) ? Wk : Wv);
        float4 v = src[p];
        int k = p >> 5;
        int nq = p & 31;
        float* dst = g_wt + (size_t)z * EE * DD;
        dst[(size_t)(4*nq + 0)*EE + k] = f2tff(v.x);
        dst[(size_t)(4*nq + 1)*EE + k] = f2tff(v.y);
        dst[(size_t)(4*nq + 2)*EE + k] = f2tff(v.z);
        dst[(size_t)(4*nq + 3)*EE + k] = f2tff(v.w);
    } else {
        int j2 = i - 3*NW;                 // init V^T rows 128..135
        if (j2 < BB*8*(TT/2)) {
            int b = j2 >> 13;              // 8*1024 words per batch
            int row = 128 + ((j2 >> 10) & 7);
            int wc = j2 & 1023;
            unsigned val = (row == 128) ? 0x3C003C00u : 0u;   // 1.0h pair or 0
            reinterpret_cast<unsigned*>(g_vTh)[(((size_t)b*VTROWS + row)*TT >> 1) + wc] = val;
        }
    }
}

// ---------------------------------------------------------------------------
// Kernel 1: QKV projection (tf32 mma, ldmatrix, 3-stage cp.async).
// z==0 epilogue folds scale*log2e; z==2 writes V^T fp16.
// ---------------------------------------------------------------------------
#define AP 36
#define BP2 36
#define A_ST (128*AP)
#define B_ST (128*BP2)

__global__ __launch_bounds__(256, 2) void proj_kernel(const float* __restrict__ x)
{
    extern __shared__ unsigned psm[];
    unsigned* As = psm;
    unsigned* Bs = psm + 3*A_ST;

    const int tid = threadIdx.x;
    const int wid = tid >> 5;
    const int lane = tid & 31;
    const int r = lane >> 2;
    const int c = lane & 3;
    const int g8 = lane >> 3;
    const int rw = lane & 7;
    const int mi = wid >> 2;
    const int nj = wid & 3;
    const int z = blockIdx.x;
    const int m0 = blockIdx.y * 128;

    const float* Wz = g_wt + (size_t)z * EE * DD;

    auto load_tile = [&](int st, int k0) {
#pragma unroll
        for (int it = 0; it < 4; ++it) {
            int linear = tid + 256 * it;
            int m = linear >> 3, g = linear & 7;
            cpa16(&As[st*A_ST + m*AP + 4*g], &x[(size_t)(m0 + m)*EE + k0 + 4*g]);
        }
#pragma unroll
        for (int it = 0; it < 4; ++it) {
            int linear = tid + 256 * it;
            int n = linear >> 3, g = linear & 7;
            cpa16(&Bs[st*B_ST + n*BP2 + 4*g], &Wz[(size_t)n*EE + k0 + 4*g]);
        }
    };

    load_tile(0, 0);  cp_commit();
    load_tile(1, 32); cp_commit();

    float acc[4][4][4];
#pragma unroll
    for (int mt = 0; mt < 4; ++mt)
#pragma unroll
        for (int nt = 0; nt < 4; ++nt)
#pragma unroll
            for (int f = 0; f < 4; ++f) acc[mt][nt][f] = 0.f;

    const int aoff = (64*mi + (g8 & 1)*8 + rw)*AP + (g8 >> 1)*4;
    const int boff = (32*nj + 8*(g8 >> 1) + rw)*BP2 + 4*(g8 & 1);

    for (int kt = 0; kt < 32; ++kt) {
        cp_wait<1>();
        __syncthreads();
        if (kt + 2 < 32) load_tile((kt + 2) % 3, 32 * (kt + 2));
        cp_commit();

        const unsigned* A = As + (kt % 3) * A_ST;
        const unsigned* B = Bs + (kt % 3) * B_ST;
#pragma unroll
        for (int kk = 0; kk < 4; ++kk) {
            unsigned a[4][4], b[4][2];
#pragma unroll
            for (int mt = 0; mt < 4; ++mt) {
                ldm4(a[mt][0], a[mt][1], a[mt][2], a[mt][3],
                     A + aoff + mt*16*AP + 8*kk);
#pragma unroll
                for (int i = 0; i < 4; ++i)
                    a[mt][i] = f2tf(__uint_as_float(a[mt][i]));
            }
            ldm4(b[0][0], b[0][1], b[1][0], b[1][1], B + boff + 8*kk);
            ldm4(b[2][0], b[2][1], b[3][0], b[3][1], B + boff + 16*BP2 + 8*kk);
#pragma unroll
            for (int mt = 0; mt < 4; ++mt)
#pragma unroll
                for (int nt = 0; nt < 4; ++nt)
                    mma8(acc[mt][nt], a[mt], b[nt]);
        }
    }

    if (z == 2) {
        // write V^T fp16: g_vTh[b][d][t]
#pragma unroll
        for (int mt = 0; mt < 4; ++mt) {
            int row0 = m0 + 64 * mi + 16 * mt + r;
            __half* vt = g_vTh + (size_t)(row0 >> 11) * VTROWS * TT;
            int t = row0 & (TT - 1);
#pragma unroll
            for (int nt = 0; nt < 4; ++nt) {
                int col = 32 * nj + 8 * nt + 2 * c;
                vt[(size_t)col * TT + t]           = __float2half(acc[mt][nt][0]);
                vt[(size_t)(col + 1) * TT + t]     = __float2half(acc[mt][nt][1]);
                vt[(size_t)col * TT + t + 8]       = __float2half(acc[mt][nt][2]);
                vt[(size_t)(col + 1) * TT + t + 8] = __float2half(acc[mt][nt][3]);
            }
        }
    } else {
        float* out = (z == 0) ? g_q : g_k;
        const float mul = (z == 0) ? SCALE_L2E : 1.f;   // fold scale*log2e into q
#pragma unroll
        for (int mt = 0; mt < 4; ++mt) {
            int row0 = m0 + 64 * mi + 16 * mt + r;
#pragma unroll
            for (int nt = 0; nt < 4; ++nt) {
                int col = 32 * nj + 8 * nt + 2 * c;
                *(float2*)&out[(size_t)row0 * DD + col] =
                    make_float2(f2tff(acc[mt][nt][0]*mul), f2tff(acc[mt][nt][1]*mul));
                *(float2*)&out[(size_t)(row0 + 8) * DD + col] =
                    make_float2(f2tff(acc[mt][nt][2]*mul), f2tff(acc[mt][nt][3]*mul));
            }
        }
    }
}

// ---------------------------------------------------------------------------
// Kernel 2: causal flash attention. S in tf32 (base-2 scores), P/V fp16,
// exp via ex2.approx.f16x2, l via ones-row of V^T (accumulated in oacc[.][8]).
// ---------------------------------------------------------------------------
#define QP 132
#define KP 132
#define VTPH 36     // fp16 V^T row: 64 fp16 = 32 words + pad
#define PPH 36      // fp16 P row: 64 fp16 = 32 words + pad
#define Q_SZ (128*QP)
#define K_SZ (64*KP)
#define VT_SZ (VTROWS*VTPH)
#define P_SZ (128*PPH)
#define OFF_K  Q_SZ
#define OFF_VT (OFF_K + K_SZ)
#define OFF_P  (OFF_VT + 2*VT_SZ)
#define OFF_MX (OFF_P + P_SZ)
#define OFF_SS (OFF_MX + 256)
#define ATTN_SMEM_W (OFF_SS + 128)

__global__ __launch_bounds__(256) void attn_kernel(float* __restrict__ out)
{
    extern __shared__ unsigned sm[];
    unsigned* Qs = sm;
    unsigned* Ks = sm + OFF_K;
    unsigned* Ps = sm + OFF_P;
    float* smax = (float*)(sm + OFF_MX);
    float* ssum = (float*)(sm + OFF_SS);

    const int ch = blockIdx.x;
    const int qt = (QTN - 1) - blockIdx.y;
    const int b  = blockIdx.z;
    const int nT = 2*qt + 2;
    const int tgS = ch*CH;
    if (tgS >= nT) return;
    const int tgE = (tgS + CH < nT) ? (tgS + CH) : nT;
    const bool direct = (tgS == 0) && (tgE == nT);
    const int t0 = qt * BR;
    const size_t base = (size_t)b * TT;

    const int tid = threadIdx.x;
    const int wid = tid >> 5;
    const int lane = tid & 31;
    const int r = lane >> 2;
    const int c = lane & 3;
    const int g8 = lane >> 3;
    const int rw = lane & 7;
    const int mi = wid & 3;
    const int ni = wid >> 2;

    auto load_k = [&](int s0) {
#pragma unroll
        for (int it = 0; it < 8; ++it) {
            int linear = tid + 256 * it;
            int row = linear >> 5, g = linear & 31;
            cpa16(&Ks[row*KP + 4*g], &g_k[(base + s0 + row)*DD + 4*g]);
        }
    };
    auto load_vt = [&](int st, int s0) {
        unsigned* Vd = sm + OFF_VT + st*VT_SZ;
#pragma unroll
        for (int it = 0; it < 5; ++it) {            // 136 rows x 8 x16B = 1088
            int linear = tid + 256 * it;
            if (linear < VTROWS*8) {
                int row = linear >> 3, g = linear & 7;
                cpa16(&Vd[row*VTPH + 4*g],
                      &g_vTh[((size_t)b*VTROWS + row)*TT + s0 + 8*g]);
            }
        }
    };

    // prologue
#pragma unroll
    for (int it = 0; it < 16; ++it) {
        int linear = tid + 256 * it;
        int row = linear >> 5, g = linear & 31;
        cpa16(&Qs[row*QP + 4*g], &g_q[(base + t0 + row)*DD + 4*g]);
    }
    load_k(BC*tgS);
    load_vt(0, BC*tgS);
    cp_commit();

    float oacc[2][9][4];
#pragma unroll
    for (int mt = 0; mt < 2; ++mt)
#pragma unroll
        for (int nt = 0; nt < 9; ++nt)
#pragma unroll
            for (int f = 0; f < 4; ++f) oacc[mt][nt][f] = 0.f;
    float m_run[4] = {-INFINITY, -INFINITY, -INFINITY, -INFINITY};

    const int qoff = (32*mi + (g8 & 1)*8 + rw)*QP + (g8 >> 1)*4;
    const int koff = (32*ni + 8*(g8 >> 1) + rw)*KP + 4*(g8 & 1);
    const int poff = (32*mi + (g8 & 1)*8 + rw)*PPH + (g8 >> 1)*4;
    const int voff = (64*ni + (g8 >> 1)*8 + rw)*VTPH + (g8 & 1)*4;
    const int vloff = (128 + rw)*VTPH + ((lane >> 3) & 1)*4;   // ones-tile rows

    for (int tg = tgS, tt = 0; tg < tgE; ++tg, ++tt) {
        cp_wait<0>();
        __syncthreads();
        const unsigned* Vc = sm + OFF_VT + (tt & 1)*VT_SZ;
        if (tg + 1 < tgE) load_vt((tt + 1) & 1, BC*(tg + 1));
        cp_commit();

        const int s0 = BC*tg;

        // ---- S = Q K^T (tf32, base-2 domain) ----
        float sacc[2][4][4];
#pragma unroll
        for (int mt = 0; mt < 2; ++mt)
#pragma unroll
            for (int nt = 0; nt < 4; ++nt)
#pragma unroll
                for (int f = 0; f < 4; ++f) sacc[mt][nt][f] = 0.f;

#pragma unroll
        for (int kc = 0; kc < 16; ++kc) {
            unsigned qa[8], kb[4][2];
            ldm4(qa[0], qa[1], qa[2], qa[3], Qs + qoff + 8*kc);
            ldm4(qa[4], qa[5], qa[6], qa[7], Qs + qoff + 16*QP + 8*kc);
            ldm4(kb[0][0], kb[0][1], kb[1][0], kb[1][1], Ks + koff + 8*kc);
            ldm4(kb[2][0], kb[2][1], kb[3][0], kb[3][1], Ks + koff + 16*KP + 8*kc);
#pragma unroll
            for (int mt = 0; mt < 2; ++mt)
#pragma unroll
                for (int nt = 0; nt < 4; ++nt)
                    mma8(sacc[mt][nt], qa + 4*mt, kb[nt]);
        }

        // ---- causal mask ----
        if (tg >= 2*qt) {
#pragma unroll
            for (int mt = 0; mt < 2; ++mt)
#pragma unroll
                for (int nt = 0; nt < 4; ++nt)
#pragma unroll
                    for (int f = 0; f < 4; ++f) {
                        int rowg = t0 + 32*mi + 16*mt + r + ((f >= 2) ? 8 : 0);
                        int colg = s0 + 32*ni + 8*nt + 2*c + (f & 1);
                        if (colg > rowg) sacc[mt][nt][f] = -1e30f;
                    }
        }

        // ---- row max exchange (ni pair) ----
        float pmax[4];
#pragma unroll
        for (int mt = 0; mt < 2; ++mt)
#pragma unroll
            for (int h = 0; h < 2; ++h) {
                float mx = -INFINITY;
#pragma unroll
                for (int nt = 0; nt < 4; ++nt) {
                    mx = fmaxf(mx, sacc[mt][nt][2*h]);
                    mx = fmaxf(mx, sacc[mt][nt][2*h + 1]);
                }
                mx = fmaxf(mx, __shfl_xor_sync(0xffffffffu, mx, 1));
                mx = fmaxf(mx, __shfl_xor_sync(0xffffffffu, mx, 2));
                pmax[2*mt + h] = mx;
            }
        if (c == 0) {
#pragma unroll
            for (int s = 0; s < 4; ++s)
                smax[ni*128 + 32*mi + 16*(s >> 1) + r + 8*(s & 1)] = pmax[s];
        }
        asm volatile("bar.sync %0, 64;" :: "r"(1 + mi));

        float m_new[4], alpha[4];
#pragma unroll
        for (int s = 0; s < 4; ++s) {
            int row = 32*mi + 16*(s >> 1) + r + 8*(s & 1);
            float mo = fmaxf(smax[row], smax[128 + row]);
            m_new[s] = fmaxf(m_run[s], mo);
            alpha[s] = ex2f(m_run[s] - m_new[s]);
            m_run[s] = m_new[s];
        }

        // ---- P = exp2(S - m) as fp16x2 (ONE MUFU per pair), no row sums ----
#pragma unroll
        for (int mt = 0; mt < 2; ++mt)
#pragma unroll
            for (int h = 0; h < 2; ++h) {
                const int s = 2*mt + h;
#pragma unroll
                for (int nt = 0; nt < 4; ++nt) {
                    unsigned pe = exp2_f16x2(sacc[mt][nt][2*h] - m_new[s],
                                             sacc[mt][nt][2*h + 1] - m_new[s]);
                    Ps[(32*mi + 16*mt + 8*h + r)*PPH + 16*ni + 4*nt + c] = pe;
                }
            }

        __syncthreads();             // P visible; K reads finished
        if (tg + 1 < tgE) load_k(BC*(tg + 1));
        cp_commit();

        // ---- rescale O (incl. l column) ----
#pragma unroll
        for (int mt = 0; mt < 2; ++mt)
#pragma unroll
            for (int nt = 0; nt < 9; ++nt) {
                oacc[mt][nt][0] *= alpha[2*mt];
                oacc[mt][nt][1] *= alpha[2*mt];
                oacc[mt][nt][2] *= alpha[2*mt + 1];
                oacc[mt][nt][3] *= alpha[2*mt + 1];
            }

        // ---- O += P V (fp16 mma, k16) ----
#pragma unroll
        for (int kc2 = 0; kc2 < 4; ++kc2) {
            unsigned pa[2][4];
            ldm4(pa[0][0], pa[0][1], pa[0][2], pa[0][3], Ps + poff + 8*kc2);
            ldm4(pa[1][0], pa[1][1], pa[1][2], pa[1][3], Ps + poff + 16*PPH + 8*kc2);
#pragma unroll
            for (int pr = 0; pr < 4; ++pr) {
                unsigned vb[4];
                ldm4(vb[0], vb[1], vb[2], vb[3], Vc + voff + pr*16*VTPH + 8*kc2);
#pragma unroll
                for (int mt = 0; mt < 2; ++mt) {
                    mma16(oacc[mt][2*pr],     pa[mt], vb);
                    mma16(oacc[mt][2*pr + 1], pa[mt], vb + 2);
                }
            }
            if (ni) {                 // ones tile -> l column
                unsigned vl[2];
                ldm2(vl[0], vl[1], Vc + vloff + 8*kc2);
                mma16(oacc[0][8], pa[0], vl);
                mma16(oacc[1][8], pa[1], vl);
            }
        }
    }

    // ---- epilogue: l from oacc[.][8] (ni==1), share, normalize/store ----
    if (ni == 1 && c == 0) {
#pragma unroll
        for (int mt = 0; mt < 2; ++mt) {
            ssum[32*mi + 16*mt + r]     = oacc[mt][8][0];
            ssum[32*mi + 16*mt + 8 + r] = oacc[mt][8][2];
        }
    }
    asm volatile("bar.sync %0, 64;" :: "r"(1 + mi));

    if (direct) {
        float inv[4];
#pragma unroll
        for (int s = 0; s < 4; ++s)
            inv[s] = 1.f / ssum[32*mi + 16*(s >> 1) + r + 8*(s & 1)];
#pragma unroll
        for (int mt = 0; mt < 2; ++mt) {
            int row0 = 32*mi + 16*mt + r;
#pragma unroll
            for (int nt = 0; nt < 8; ++nt) {
                int col = 64*ni + 8*nt + 2*c;
                size_t gr = base + t0 + row0;
                *(float2*)&out[gr*DD + col] =
                    make_float2(oacc[mt][nt][0]*inv[2*mt], oacc[mt][nt][1]*inv[2*mt]);
                *(float2*)&out[(gr + 8)*DD + col] =
                    make_float2(oacc[mt][nt][2]*inv[2*mt+1], oacc[mt][nt][3]*inv[2*mt+1]);
            }
        }
        return;
    }

    const int slot = (qt*NCMAX + ch)*BB + b;
    if (ni == 0 && c == 0) {
#pragma unroll
        for (int s = 0; s < 4; ++s) {
            int row = 32*mi + 16*(s >> 1) + r + 8*(s & 1);
            g_ml[slot*256 + row]       = m_run[s];       // log2 domain
            g_ml[slot*256 + 128 + row] = ssum[row];
        }
    }
    float* op = g_Op + (size_t)slot * BR * DD;
#pragma unroll
    for (int mt = 0; mt < 2; ++mt) {
        int row0 = 32*mi + 16*mt + r;
#pragma unroll
        for (int nt = 0; nt < 8; ++nt) {
            int col = 64*ni + 8*nt + 2*c;
            *(float2*)&op[(size_t)row0*DD + col] =
                make_float2(oacc[mt][nt][0], oacc[mt][nt][1]);
            *(float2*)&op[(size_t)(row0 + 8)*DD + col] =
                make_float2(oacc[mt][nt][2], oacc[mt][nt][3]);
        }
    }
}

// ---------------------------------------------------------------------------
// Kernel 3: combine chunk partials (log2-domain weights).
// ---------------------------------------------------------------------------
__global__ __launch_bounds__(256) void combine_kernel(float* __restrict__ out)
{
    const int blk = blockIdx.x;
    const int rg = blk & 7;
    const int qb = blk >> 3;
    const int qt = qb >> 3, b = qb & 7;
    const int nT = 2*qt + 2;
    const int nc = (nT + CH - 1) / CH;
    if (nc == 1) return;
    const int tid = threadIdx.x;
    const int row = rg*16 + (tid >> 4);
    const int seg = (tid & 15) * 8;
    const int t0 = qt * BR;

    float M = -INFINITY;
    for (int cc = 0; cc < nc; ++cc)
        M = fmaxf(M, g_ml[((qt*NCMAX + cc)*BB + b)*256 + row]);
    float L = 0.f;
    for (int cc = 0; cc < nc; ++cc) {
        int slot = (qt*NCMAX + cc)*BB + b;
        L += ex2f(g_ml[slot*256 + row] - M) * g_ml[slot*256 + 128 + row];
    }
    const float inv = 1.f / L;

    float4 a0 = make_float4(0.f,0.f,0.f,0.f), a1 = a0;
    for (int cc = 0; cc < nc; ++cc) {
        int slot = (qt*NCMAX + cc)*BB + b;
        float w = ex2f(g_ml[slot*256 + row] - M);
        const float4* src = (const float4*)&g_Op[((size_t)slot*BR + row)*DD + seg];
        float4 v0 = src[0], v1 = src[1];
        a0.x += w*v0.x; a0.y += w*v0.y; a0.z += w*v0.z; a0.w += w*v0.w;
        a1.x += w*v1.x; a1.y += w*v1.y; a1.z += w*v1.z; a1.w += w*v1.w;
    }
    float4* dst = (float4*)&out[((size_t)b*TT + t0 + row)*DD + seg];
    a0.x *= inv; a0.y *= inv; a0.z *= inv; a0.w *= inv;
    a1.x *= inv; a1.y *= inv; a1.z *= inv; a1.w *= inv;
    dst[0] = a0; dst[1] = a1;
}

// ---------------------------------------------------------------------------
extern "C" void kernel_launch(void* const* d_in, const int* in_sizes, int n_in,
                              void* d_out, int out_size)
{
    (void)in_sizes; (void)n_in; (void)out_size;
    const float* x  = (const float*)d_in[0];
    const float* Wk = (const float*)d_in[1];
    const float* Wq = (const float*)d_in[2];
    const float* Wv = (const float*)d_in[3];
    float* out = (float*)d_out;

    const int nCvt = (3*EE*DD/4 + BB*8*(TT/2) + 255) / 256;
    cvt_w_kernel<<<nCvt, 256>>>(Wk, Wq, Wv);

    const int proj_smem = (3*A_ST + 3*B_ST) * 4;
    cudaFuncSetAttribute(proj_kernel,
                         cudaFuncAttributeMaxDynamicSharedMemorySize, proj_smem);
    dim3 pgrid(3, BT/128);
    proj_kernel<<<pgrid, 256, proj_smem>>>(x);

    const int attn_smem = ATTN_SMEM_W * 4;   // ~160.5 KB
    cudaFuncSetAttribute(attn_kernel,
                         cudaFuncAttributeMaxDynamicSharedMemorySize, attn_smem);
    dim3 agrid(NCMAX, QTN, BB);
    attn_kernel<<<agrid, 256, attn_smem>>>(out);

    combine_kernel<<<QTN*BB*8, 256>>>(out);
}